// round 1
// baseline (speedup 1.0000x reference)
#include <cuda_runtime.h>
#include <math.h>

// ----------------------------------------------------------------------------
// RNN: h_t = tanh(x_t @ Wi^T + bi + h_{t-1} @ Wh^T + bh)
// Phase 1: xi = x @ Wi^T + bi for all timesteps (one big GEMM) -> stored in d_out
// Phase 2: 512 sequential step GEMMs, each reading xi[t] (in d_out) and
//          h_{t-1} (previous d_out row block, or h0), overwriting d_out[t] with h_t.
// Both GEMMs are "NT": A[M,K] row-major, B[N,K] row-major (K contiguous in both).
// ----------------------------------------------------------------------------

template <int V>
__device__ __forceinline__ void lds_vec(float* dst, const float* src) {
    if constexpr (V % 4 == 0) {
#pragma unroll
        for (int i = 0; i < V; i += 4) {
            float4 t = *reinterpret_cast<const float4*>(src + i);
            dst[i + 0] = t.x; dst[i + 1] = t.y; dst[i + 2] = t.z; dst[i + 3] = t.w;
        }
    } else if constexpr (V % 2 == 0) {
#pragma unroll
        for (int i = 0; i < V; i += 2) {
            float2 t = *reinterpret_cast<const float2*>(src + i);
            dst[i + 0] = t.x; dst[i + 1] = t.y;
        }
    } else {
#pragma unroll
        for (int i = 0; i < V; ++i) dst[i] = src[i];
    }
}

// C[m,n] = act( sum_k A[m,k]*B[n,k] + bias[n] (+ Cadd[m,n]) )
// Requires: M % BM == 0, N % BN == 0, K % BK == 0, BK % 4 == 0.
template <int BM, int BN, int BK, int TM, int TN, bool TANH, bool ADD>
__global__ void __launch_bounds__((BM / TM) * (BN / TN))
gemm_nt_kernel(const float* __restrict__ A,
               const float* __restrict__ B,
               const float* __restrict__ bias,
               const float* Cadd,   // may alias C (each elem read-before-write by owner thread)
               float* C,
               int M, int N, int K)
{
    constexpr int THREADS = (BM / TM) * (BN / TN);
    constexpr int KV = BK / 4;                      // float4 chunks per K-row of a tile
    constexpr int A_LOADS = (BM * KV) / THREADS;    // float4 loads per thread (A tile)
    constexpr int B_LOADS = (BN * KV) / THREADS;    // float4 loads per thread (B tile)
    static_assert((BM * KV) % THREADS == 0, "A tile load imbalance");
    static_assert((BN * KV) % THREADS == 0, "B tile load imbalance");

    // +4 pad keeps 16B alignment of each k-row while breaking store conflicts
    __shared__ float As[BK][BM + 4];
    __shared__ float Bs[BK][BN + 4];

    const int tid = threadIdx.x;
    const int tx  = tid % (BN / TN);
    const int ty  = tid / (BN / TN);

    const int block_m = blockIdx.y * BM;
    const int block_n = blockIdx.x * BN;

    float acc[TM][TN];
#pragma unroll
    for (int i = 0; i < TM; ++i)
#pragma unroll
        for (int j = 0; j < TN; ++j) acc[i][j] = 0.f;

    for (int kt = 0; kt < K; kt += BK) {
        // ---- load A tile (BM x BK), store transposed As[k][m] ----
#pragma unroll
        for (int l = 0; l < A_LOADS; ++l) {
            int f  = tid + l * THREADS;
            int r  = f / KV;
            int c4 = f % KV;
            float4 v = *reinterpret_cast<const float4*>(
                A + (size_t)(block_m + r) * K + kt + c4 * 4);
            As[c4 * 4 + 0][r] = v.x;
            As[c4 * 4 + 1][r] = v.y;
            As[c4 * 4 + 2][r] = v.z;
            As[c4 * 4 + 3][r] = v.w;
        }
        // ---- load B tile (BN x BK), store transposed Bs[k][n] ----
#pragma unroll
        for (int l = 0; l < B_LOADS; ++l) {
            int f  = tid + l * THREADS;
            int r  = f / KV;
            int c4 = f % KV;
            float4 v = *reinterpret_cast<const float4*>(
                B + (size_t)(block_n + r) * K + kt + c4 * 4);
            Bs[c4 * 4 + 0][r] = v.x;
            Bs[c4 * 4 + 1][r] = v.y;
            Bs[c4 * 4 + 2][r] = v.z;
            Bs[c4 * 4 + 3][r] = v.w;
        }
        __syncthreads();

#pragma unroll
        for (int k = 0; k < BK; ++k) {
            float a[TM], b[TN];
            lds_vec<TM>(a, &As[k][ty * TM]);
            lds_vec<TN>(b, &Bs[k][tx * TN]);
#pragma unroll
            for (int i = 0; i < TM; ++i)
#pragma unroll
                for (int j = 0; j < TN; ++j)
                    acc[i][j] = fmaf(a[i], b[j], acc[i][j]);
        }
        __syncthreads();
    }

    // ---- epilogue: bias (+ addend) (+ tanh) ----
#pragma unroll
    for (int i = 0; i < TM; ++i) {
        const int m = block_m + ty * TM + i;
#pragma unroll
        for (int j = 0; j < TN; ++j) {
            const int n = block_n + tx * TN + j;
            float v = acc[i][j] + bias[n];
            if (ADD) v += Cadd[(size_t)m * N + n];
            if (TANH) v = tanhf(v);
            C[(size_t)m * N + n] = v;
        }
    }
}

extern "C" void kernel_launch(void* const* d_in, const int* in_sizes, int n_in,
                              void* d_out, int out_size)
{
    const float* x    = (const float*)d_in[0];  // [L,B,D]
    const float* h0   = (const float*)d_in[1];  // [B,H]
    const float* Wi_w = (const float*)d_in[2];  // [H,D]
    const float* Wi_b = (const float*)d_in[3];  // [H]
    const float* Wh_w = (const float*)d_in[4];  // [H,H]
    const float* Wh_b = (const float*)d_in[5];  // [H]
    float* out = (float*)d_out;                 // [L,B,H]

    const int H = in_sizes[3];
    const int B = in_sizes[1] / H;
    const int D = in_sizes[2] / H;
    const int L = in_sizes[0] / (B * D);
    const int M1 = L * B;
    const size_t BH = (size_t)B * H;

    // ---- Phase 1: out = x @ Wi^T + bi  (M=L*B, N=H, K=D) ----
    {
        dim3 grid(H / 64, M1 / 128);
        gemm_nt_kernel<128, 64, 16, 8, 4, /*TANH=*/false, /*ADD=*/false>
            <<<grid, 256>>>(x, Wi_w, Wi_b, nullptr, out, M1, H, D);
    }

    // ---- Phase 2: sequential recurrence (M=B, N=H, K=H), in-place on out[t] ----
    for (int t = 0; t < L; ++t) {
        const float* hprev = (t == 0) ? h0 : (out + (size_t)(t - 1) * BH);
        float* ct = out + (size_t)t * BH;
        dim3 grid(H / 64, B / 16);
        gemm_nt_kernel<16, 64, 32, 2, 4, /*TANH=*/true, /*ADD=*/true>
            <<<grid, 128>>>(hprev, Wh_w, Wh_b, ct, ct, B, H, H);
    }
}

// round 3
// speedup vs baseline: 1.5054x; 1.5054x over previous
#include <cuda_runtime.h>
#include <math.h>

// ============================================================================
// RNN: h_t = tanh(x_t @ Wi^T + bi + h_{t-1} @ Wh^T + bh)
// Phase 1: one big SGEMM xi = x @ Wi^T + bi  -> d_out  (parallel over L*B)
// Phase 2: ONE persistent kernel, 128 CTAs (1/SM), 512 steps with a software
//          global barrier per step. Each CTA owns 8 output columns; its Wh
//          slice (8x1024 = 32KB) lives in SMEM for the whole kernel. h_{t-1}
//          is streamed from L2 through double-buffered SMEM via cp.async.
// Phase 3: tiny kernel resets barrier counters (graph-replay safe).
// Shapes hardcoded for this problem: L=512, B=128, D=H=1024 (fp32).
// ============================================================================

#define L_    512
#define B_    128
#define H_    1024
#define NCTA  128
#define BLK   128          // threads per step-CTA
#define COLS  8            // output columns per CTA (NCTA*COLS == H_)
#define KT    128          // k-chunk per smem stage
#define NCH   (H_ / KT)    // 8 chunks per step
#define HS_STRIDE 132      // KT+4: keeps 16B alignment (132*4%16==0) and
                           // conflict-free h reads with rows strided by 32

__device__ unsigned g_cnt[L_];   // zero-initialized at module load; reset by reset_cnt

// ---------------- cp.async helpers ----------------
__device__ __forceinline__ void cp_async16(float* smem_dst, const float* gsrc) {
    unsigned s = (unsigned)__cvta_generic_to_shared(smem_dst);
    asm volatile("cp.async.cg.shared.global [%0], [%1], 16;\n" :: "r"(s), "l"(gsrc));
}
__device__ __forceinline__ void cp_commit() {
    asm volatile("cp.async.commit_group;\n");
}
template <int N>
__device__ __forceinline__ void cp_wait() {
    asm volatile("cp.async.wait_group %0;\n" :: "n"(N));
}

// Issue one 128x128-float chunk of h_prev (rows 0..127, cols ch*KT..) into dst.
__device__ __forceinline__ void issue_chunk(const float* __restrict__ hp, int ch,
                                            float* __restrict__ dst, int tid) {
#pragma unroll
    for (int f = tid; f < B_ * KT / 4; f += BLK) {   // 4096 float4 slots, 32/thread
        int b  = f >> 5;        // KT/4 == 32 float4 per row
        int kv = f & 31;
        cp_async16(dst + b * HS_STRIDE + kv * 4, hp + ch * KT + (size_t)b * H_ + kv * 4);
    }
}

// ---------------- persistent recurrence kernel ----------------
__global__ void __launch_bounds__(BLK, 1)
rnn_steps(const float* __restrict__ h0, const float* __restrict__ Wh,
          const float* __restrict__ bh, float* __restrict__ out)
{
    extern __shared__ float smem[];
    float* wsm  = smem;                 // [H_][COLS] flat: wsm[k*COLS + j]
    float* hbuf = smem + H_ * COLS;     // 2 x [B_][HS_STRIDE]

    const int tid = threadIdx.x;
    const int n0  = blockIdx.x * COLS;

    // Load this CTA's Wh slice once: wsm[k*8+j] = Wh[(n0+j)*H + k]
    for (int idx = tid; idx < COLS * (H_ / 4); idx += BLK) {
        int j  = idx >> 8;            // / (H_/4)
        int kv = idx & 255;
        float4 v = *reinterpret_cast<const float4*>(Wh + (size_t)(n0 + j) * H_ + kv * 4);
        wsm[(kv * 4 + 0) * COLS + j] = v.x;
        wsm[(kv * 4 + 1) * COLS + j] = v.y;
        wsm[(kv * 4 + 2) * COLS + j] = v.z;
        wsm[(kv * 4 + 3) * COLS + j] = v.w;
    }

    const int cg = tid & 3;            // column group (2 cols each)
    const int bg = tid >> 2;           // row group (rows bg, bg+32, bg+64, bg+96)
    const int c0 = cg * 2;
    const float wb0 = bh[n0 + c0];
    const float wb1 = bh[n0 + c0 + 1];
    __syncthreads();

    for (int t = 0; t < L_; ++t) {
        const float* hp = (t == 0) ? h0 : (out + (size_t)(t - 1) * B_ * H_);

        issue_chunk(hp, 0, hbuf, tid);                      cp_commit();
        issue_chunk(hp, 1, hbuf + B_ * HS_STRIDE, tid);     cp_commit();

        float acc[4][2] = {{0.f,0.f},{0.f,0.f},{0.f,0.f},{0.f,0.f}};

#pragma unroll 1
        for (int ch = 0; ch < NCH; ++ch) {
            if (ch < NCH - 1) cp_wait<1>(); else cp_wait<0>();
            __syncthreads();
            const float* hb = hbuf + (ch & 1) * B_ * HS_STRIDE;
            const float* wp = wsm + ch * KT * COLS + c0;
#pragma unroll 8
            for (int k = 0; k < KT; ++k) {
                float2 w = *reinterpret_cast<const float2*>(wp + k * COLS);
#pragma unroll
                for (int i = 0; i < 4; ++i) {
                    float h = hb[(bg + 32 * i) * HS_STRIDE + k];
                    acc[i][0] = fmaf(h, w.x, acc[i][0]);
                    acc[i][1] = fmaf(h, w.y, acc[i][1]);
                }
            }
            __syncthreads();
            if (ch + 2 < NCH) {
                issue_chunk(hp, ch + 2, hbuf + (ch & 1) * B_ * HS_STRIDE, tid);
                cp_commit();
            }
        }

        // Epilogue: in-place xi -> h (each element read+written by its owner thread)
        float* ot = out + (size_t)t * B_ * H_;
#pragma unroll
        for (int i = 0; i < 4; ++i) {
            int b = bg + 32 * i;
            size_t base = (size_t)b * H_ + n0 + c0;
            float v0 = tanhf(acc[i][0] + wb0 + ot[base]);
            float v1 = tanhf(acc[i][1] + wb1 + ot[base + 1]);
            ot[base]     = v0;
            ot[base + 1] = v1;
        }

        // Global barrier (skip after the last step; counters reset by reset_cnt)
        if (t < L_ - 1) {
            __threadfence();          // publish my STG gpu-wide
            __syncthreads();
            if (tid == 0) {
                atomicAdd(&g_cnt[t], 1u);
                while (((volatile unsigned*)g_cnt)[t] < NCTA) {
                    __nanosleep(64);  // back off: don't hammer the LTS atomic ALU
                }
                __threadfence();      // acquire
            }
            __syncthreads();
        }
    }
}

__global__ void reset_cnt() {
    int i = blockIdx.x * blockDim.x + threadIdx.x;
    if (i < L_) g_cnt[i] = 0;
}

// ---------------- Phase-1 SGEMM (NT, fused bias) ----------------
template <int V>
__device__ __forceinline__ void lds_vec(float* dst, const float* src) {
#pragma unroll
    for (int i = 0; i < V; i += 4) {
        float4 t = *reinterpret_cast<const float4*>(src + i);
        dst[i + 0] = t.x; dst[i + 1] = t.y; dst[i + 2] = t.z; dst[i + 3] = t.w;
    }
}

template <int BM, int BN, int BK, int TM, int TN>
__global__ void __launch_bounds__((BM / TM) * (BN / TN))
gemm_nt_bias(const float* __restrict__ A, const float* __restrict__ B,
             const float* __restrict__ bias, float* __restrict__ C,
             int M, int N, int K)
{
    constexpr int THREADS = (BM / TM) * (BN / TN);
    constexpr int KV = BK / 4;
    constexpr int A_LOADS = (BM * KV) / THREADS;
    constexpr int B_LOADS = (BN * KV) / THREADS;

    __shared__ float As[BK][BM + 4];
    __shared__ float Bs[BK][BN + 4];

    const int tid = threadIdx.x;
    const int tx  = tid % (BN / TN);
    const int ty  = tid / (BN / TN);
    const int block_m = blockIdx.y * BM;
    const int block_n = blockIdx.x * BN;

    float acc[TM][TN];
#pragma unroll
    for (int i = 0; i < TM; ++i)
#pragma unroll
        for (int j = 0; j < TN; ++j) acc[i][j] = 0.f;

    for (int kt = 0; kt < K; kt += BK) {
#pragma unroll
        for (int l = 0; l < A_LOADS; ++l) {
            int f = tid + l * THREADS;
            int r = f / KV, c4 = f % KV;
            float4 v = *reinterpret_cast<const float4*>(A + (size_t)(block_m + r) * K + kt + c4 * 4);
            As[c4 * 4 + 0][r] = v.x; As[c4 * 4 + 1][r] = v.y;
            As[c4 * 4 + 2][r] = v.z; As[c4 * 4 + 3][r] = v.w;
        }
#pragma unroll
        for (int l = 0; l < B_LOADS; ++l) {
            int f = tid + l * THREADS;
            int r = f / KV, c4 = f % KV;
            float4 v = *reinterpret_cast<const float4*>(B + (size_t)(block_n + r) * K + kt + c4 * 4);
            Bs[c4 * 4 + 0][r] = v.x; Bs[c4 * 4 + 1][r] = v.y;
            Bs[c4 * 4 + 2][r] = v.z; Bs[c4 * 4 + 3][r] = v.w;
        }
        __syncthreads();
#pragma unroll
        for (int k = 0; k < BK; ++k) {
            float a[TM], b[TN];
            lds_vec<TM>(a, &As[k][ty * TM]);
            lds_vec<TN>(b, &Bs[k][tx * TN]);
#pragma unroll
            for (int i = 0; i < TM; ++i)
#pragma unroll
                for (int j = 0; j < TN; ++j)
                    acc[i][j] = fmaf(a[i], b[j], acc[i][j]);
        }
        __syncthreads();
    }

#pragma unroll
    for (int i = 0; i < TM; ++i) {
        const int m = block_m + ty * TM + i;
#pragma unroll
        for (int j = 0; j < TN; ++j) {
            const int n = block_n + tx * TN + j;
            C[(size_t)m * N + n] = acc[i][j] + bias[n];
        }
    }
}

// ---------------- launcher ----------------
extern "C" void kernel_launch(void* const* d_in, const int* in_sizes, int n_in,
                              void* d_out, int out_size)
{
    const float* x    = (const float*)d_in[0];  // [L,B,D]
    const float* h0   = (const float*)d_in[1];  // [B,H]
    const float* Wi_w = (const float*)d_in[2];  // [H,D]
    const float* Wi_b = (const float*)d_in[3];  // [H]
    const float* Wh_w = (const float*)d_in[4];  // [H,H]
    const float* Wh_b = (const float*)d_in[5];  // [H]
    float* out = (float*)d_out;                 // [L,B,H]

    // Phase 1: out = x @ Wi^T + bi   (M = L*B = 65536, N = H = 1024, K = D = 1024)
    {
        const int M1 = L_ * B_;
        dim3 grid(H_ / 128, M1 / 128);
        gemm_nt_bias<128, 128, 16, 8, 8><<<grid, 256>>>(x, Wi_w, Wi_b, out, M1, H_, H_);
    }

    // Phase 2: persistent recurrence
    {
        const int smem_bytes = (H_ * COLS + 2 * B_ * HS_STRIDE) * (int)sizeof(float); // 167936
        cudaFuncSetAttribute(rnn_steps, cudaFuncAttributeMaxDynamicSharedMemorySize, smem_bytes);
        rnn_steps<<<NCTA, BLK, smem_bytes>>>(h0, Wh_w, Wh_b, out);
    }

    // Phase 3: reset barrier counters for the next graph replay
    reset_cnt<<<(L_ + 255) / 256, 256>>>();
}

// round 4
// speedup vs baseline: 2.2338x; 1.4838x over previous
#include <cuda_runtime.h>
#include <math.h>

// ============================================================================
// RNN: h_t = tanh(x_t @ Wi^T + bi + h_{t-1} @ Wh^T + bh)
// Phase 1: SGEMM xi = x @ Wi^T + bi -> d_out, inner loop packed with fma.rn.f32x2
// Phase 2: persistent kernel, 128 CTAs x 512 threads. Warp w owns rows 8w..8w+7
//          x 8 cols; lanes split k 32-ways (k-lane layout: all smem reads are
//          lane-contiguous -> conflict-free). Packed f32x2 FMAs; end-of-step
//          butterfly-split reduction over lanes. Global barrier per step.
// Shapes hardcoded: L=512, B=128, D=H=1024 (fp32).
// ============================================================================

#define L_    512
#define B_    128
#define H_    1024
#define NCTA  128
#define BLK2  512            // threads in step kernel (16 warps)
#define COLS  8              // output columns per CTA
#define KT    128            // k-chunk per smem stage
#define NCH   (H_ / KT)      // 8 chunks
#define HBUF  (B_ * KT)      // floats per h stage (no pad needed: contiguous reads)

typedef unsigned long long ull;

__device__ unsigned g_cnt[L_];   // zeroed at load; reset by reset_cnt each replay

// ---------------- f32x2 helpers ----------------
__device__ __forceinline__ ull pack2(float lo, float hi) {
    ull d;
    asm("mov.b64 %0, {%1, %2};" : "=l"(d) : "r"(__float_as_uint(lo)), "r"(__float_as_uint(hi)));
    return d;
}
__device__ __forceinline__ void unpack2(float& lo, float& hi, ull v) {
    unsigned a, b;
    asm("mov.b64 {%0, %1}, %2;" : "=r"(a), "=r"(b) : "l"(v));
    lo = __uint_as_float(a); hi = __uint_as_float(b);
}
__device__ __forceinline__ void fma2(ull& d, ull a, ull b) {
    asm("fma.rn.f32x2 %0, %1, %2, %0;" : "+l"(d) : "l"(a), "l"(b));
}
__device__ __forceinline__ ull add2(ull a, ull b) {
    ull d;
    asm("add.rn.f32x2 %0, %1, %2;" : "=l"(d) : "l"(a), "l"(b));
    return d;
}

// ---------------- cp.async helpers ----------------
__device__ __forceinline__ void cp_async16(float* smem_dst, const float* gsrc) {
    unsigned s = (unsigned)__cvta_generic_to_shared(smem_dst);
    asm volatile("cp.async.cg.shared.global [%0], [%1], 16;\n" :: "r"(s), "l"(gsrc));
}
__device__ __forceinline__ void cp_commit() { asm volatile("cp.async.commit_group;\n"); }
template <int N>
__device__ __forceinline__ void cp_wait() { asm volatile("cp.async.wait_group %0;\n" :: "n"(N)); }

// Stream one 128(row) x 128(k) chunk of h_prev into dst (row-major, stride KT).
__device__ __forceinline__ void issue_chunk(const float* __restrict__ hp, int ch,
                                            float* __restrict__ dst, int tid) {
#pragma unroll
    for (int f = tid; f < B_ * KT / 4; f += BLK2) {   // 4096 float4 slots, 8/thread
        int b  = f >> 5;                              // KT/4 == 32 float4 per row
        int kv = f & 31;
        cp_async16(dst + b * KT + kv * 4, hp + (size_t)b * H_ + ch * KT + kv * 4);
    }
}

// ---------------- persistent recurrence kernel ----------------
__global__ void __launch_bounds__(BLK2, 1)
rnn_steps(const float* __restrict__ h0, const float* __restrict__ Wh,
          const float* __restrict__ bh, float* __restrict__ out)
{
    extern __shared__ float smem[];
    float* wsm  = smem;                  // [COLS][H_] row-major (32KB)
    float* hbuf = smem + COLS * H_;      // 2 x [B_][KT] row-major (128KB)

    const int tid  = threadIdx.x;
    const int warp = tid >> 5;
    const int lane = tid & 31;
    const int n0   = blockIdx.x * COLS;
    const int r0   = warp * 8;           // this warp's row base

    // Load Wh slice: wsm[c][k] = Wh[(n0+c)*H + k]  (contiguous copy)
    for (int idx = tid; idx < COLS * (H_ / 4); idx += BLK2) {
        int c  = idx >> 8;               // / (H_/4)
        int kv = idx & 255;
        float4 v = *reinterpret_cast<const float4*>(Wh + (size_t)(n0 + c) * H_ + kv * 4);
        *reinterpret_cast<float4*>(wsm + c * H_ + kv * 4) = v;
    }

    // Output mapping after butterfly: lane ends holding V[rev5(lane)]
    const int j  = (int)(__brev((unsigned)lane) >> 27);  // 0..31
    const int pj = j >> 3;                               // row-pair index
    const int cj = j & 7;                                // col index
    const int row0 = r0 + 2 * pj;
    const int col  = n0 + cj;
    const float wb = bh[col];
    const size_t o_off0 = (size_t)row0 * H_ + col;       // + t*B*H per step
    __syncthreads();

    for (int t = 0; t < L_; ++t) {
        const float* hp = (t == 0) ? h0 : (out + (size_t)(t - 1) * B_ * H_);

        issue_chunk(hp, 0, hbuf, tid);        cp_commit();
        issue_chunk(hp, 1, hbuf + HBUF, tid); cp_commit();

        ull acc2[32];
#pragma unroll
        for (int i = 0; i < 32; ++i) acc2[i] = 0ull;

#pragma unroll 1
        for (int ch = 0; ch < NCH; ++ch) {
            if (ch < NCH - 1) cp_wait<1>(); else cp_wait<0>();
            __syncthreads();
            const float* hb = hbuf + (ch & 1) * HBUF;
#pragma unroll
            for (int kq = 0; kq < KT / 32; ++kq) {       // 4 own-k per chunk
                const int kl = kq * 32 + lane;           // local k in chunk
                const float* hpr = hb + (size_t)r0 * KT + kl;
                const float* wpr = wsm + ch * KT + kl;
                float h[8], w[8];
#pragma unroll
                for (int ri = 0; ri < 8; ++ri) h[ri] = hpr[ri * KT];
#pragma unroll
                for (int c = 0; c < 8; ++c)    w[c]  = wpr[c * H_];
                ull hp2[4], wd[8];
#pragma unroll
                for (int p = 0; p < 4; ++p) hp2[p] = pack2(h[2 * p], h[2 * p + 1]);
#pragma unroll
                for (int c = 0; c < 8; ++c) wd[c] = pack2(w[c], w[c]);
#pragma unroll
                for (int p = 0; p < 4; ++p)
#pragma unroll
                    for (int c = 0; c < 8; ++c)
                        fma2(acc2[p * 8 + c], hp2[p], wd[c]);
            }
            __syncthreads();
            if (ch + 2 < NCH) {
                issue_chunk(hp, ch + 2, hbuf + (ch & 1) * HBUF, tid);
                cp_commit();
            }
        }

        // Butterfly-split reduction over the 32 k-lanes.
        // After round d, each lane keeps the half of the live outputs on its side.
        int half = 16;
#pragma unroll
        for (int d = 1; d < 32; d <<= 1) {
            const bool up = (lane & d) != 0;
#pragma unroll
            for (int i = 0; i < 16; ++i) {
                if (i < half) {
                    ull send = up ? acc2[i] : acc2[i + half];
                    ull keep = up ? acc2[i + half] : acc2[i];
                    ull recv = __shfl_xor_sync(0xffffffffu, send, d);
                    acc2[i] = add2(keep, recv);
                }
            }
            half >>= 1;
        }
        // Lane now holds the full sum for output (row0,col),(row0+1,col) in acc2[0].

        float a0, a1;
        unpack2(a0, a1, acc2[0]);
        float* ot = out + (size_t)t * B_ * H_;
        float v0 = tanhf(a0 + wb + ot[o_off0]);
        float v1 = tanhf(a1 + wb + ot[o_off0 + H_]);
        ot[o_off0]      = v0;
        ot[o_off0 + H_] = v1;

        if (t < L_ - 1) {
            __threadfence();
            __syncthreads();
            if (tid == 0) {
                atomicAdd(&g_cnt[t], 1u);
                while (((volatile unsigned*)g_cnt)[t] < NCTA) { __nanosleep(64); }
                __threadfence();
            }
            __syncthreads();
        }
    }
}

__global__ void reset_cnt() {
    int i = blockIdx.x * blockDim.x + threadIdx.x;
    if (i < L_) g_cnt[i] = 0;
}

// ---------------- Phase-1 SGEMM (NT, fused bias, f32x2 inner) ----------------
template <int BM, int BN, int BK, int TM, int TN>
__global__ void __launch_bounds__((BM / TM) * (BN / TN))
gemm_nt_bias(const float* __restrict__ A, const float* __restrict__ B,
             const float* __restrict__ bias, float* __restrict__ C,
             int M, int N, int K)
{
    constexpr int THREADS = (BM / TM) * (BN / TN);
    constexpr int KV = BK / 4;
    constexpr int A_LOADS = (BM * KV) / THREADS;
    constexpr int B_LOADS = (BN * KV) / THREADS;
    static_assert(TN % 2 == 0, "TN must be even for f32x2");

    __shared__ float As[BK][BM + 4];
    __shared__ float Bs[BK][BN + 4];   // row stride (BN+4)*4 = 528B, 16B aligned

    const int tid = threadIdx.x;
    const int tx  = tid % (BN / TN);
    const int ty  = tid / (BN / TN);
    const int block_m = blockIdx.y * BM;
    const int block_n = blockIdx.x * BN;

    ull acc2[TM][TN / 2];
#pragma unroll
    for (int i = 0; i < TM; ++i)
#pragma unroll
        for (int jx = 0; jx < TN / 2; ++jx) acc2[i][jx] = 0ull;

    for (int kt = 0; kt < K; kt += BK) {
#pragma unroll
        for (int l = 0; l < A_LOADS; ++l) {
            int f = tid + l * THREADS;
            int r = f / KV, c4 = f % KV;
            float4 v = *reinterpret_cast<const float4*>(A + (size_t)(block_m + r) * K + kt + c4 * 4);
            As[c4 * 4 + 0][r] = v.x; As[c4 * 4 + 1][r] = v.y;
            As[c4 * 4 + 2][r] = v.z; As[c4 * 4 + 3][r] = v.w;
        }
#pragma unroll
        for (int l = 0; l < B_LOADS; ++l) {
            int f = tid + l * THREADS;
            int r = f / KV, c4 = f % KV;
            float4 v = *reinterpret_cast<const float4*>(B + (size_t)(block_n + r) * K + kt + c4 * 4);
            Bs[c4 * 4 + 0][r] = v.x; Bs[c4 * 4 + 1][r] = v.y;
            Bs[c4 * 4 + 2][r] = v.z; Bs[c4 * 4 + 3][r] = v.w;
        }
        __syncthreads();
#pragma unroll
        for (int k = 0; k < BK; ++k) {
            float a[TM];
#pragma unroll
            for (int i = 0; i < TM; i += 4) {
                float4 t4 = *reinterpret_cast<const float4*>(&As[k][ty * TM + i]);
                a[i + 0] = t4.x; a[i + 1] = t4.y; a[i + 2] = t4.z; a[i + 3] = t4.w;
            }
            ull bp[TN / 2];
#pragma unroll
            for (int jx = 0; jx < TN / 2; jx += 2) {
                ulonglong2 t2 = *reinterpret_cast<const ulonglong2*>(&Bs[k][tx * TN + jx * 2]);
                bp[jx + 0] = t2.x; bp[jx + 1] = t2.y;
            }
            ull ad[TM];
#pragma unroll
            for (int i = 0; i < TM; ++i) ad[i] = pack2(a[i], a[i]);
#pragma unroll
            for (int i = 0; i < TM; ++i)
#pragma unroll
                for (int jx = 0; jx < TN / 2; ++jx)
                    fma2(acc2[i][jx], ad[i], bp[jx]);
        }
        __syncthreads();
    }

#pragma unroll
    for (int i = 0; i < TM; ++i) {
        const int m = block_m + ty * TM + i;
#pragma unroll
        for (int jx = 0; jx < TN / 2; ++jx) {
            const int n = block_n + tx * TN + jx * 2;
            float lo, hi;
            unpack2(lo, hi, acc2[i][jx]);
            float2 st;
            st.x = lo + bias[n];
            st.y = hi + bias[n + 1];
            *reinterpret_cast<float2*>(C + (size_t)m * N + n) = st;
        }
    }
}

// ---------------- launcher ----------------
extern "C" void kernel_launch(void* const* d_in, const int* in_sizes, int n_in,
                              void* d_out, int out_size)
{
    const float* x    = (const float*)d_in[0];  // [L,B,D]
    const float* h0   = (const float*)d_in[1];  // [B,H]
    const float* Wi_w = (const float*)d_in[2];  // [H,D]
    const float* Wi_b = (const float*)d_in[3];  // [H]
    const float* Wh_w = (const float*)d_in[4];  // [H,H]
    const float* Wh_b = (const float*)d_in[5];  // [H]
    float* out = (float*)d_out;                 // [L,B,H]

    // Phase 1: out = x @ Wi^T + bi
    {
        const int M1 = L_ * B_;
        dim3 grid(H_ / 128, M1 / 128);
        gemm_nt_bias<128, 128, 16, 8, 8><<<grid, 256>>>(x, Wi_w, Wi_b, out, M1, H_, H_);
    }

    // Phase 2: persistent recurrence
    {
        const int smem_bytes = (COLS * H_ + 2 * HBUF) * (int)sizeof(float); // 163840
        cudaFuncSetAttribute(rnn_steps, cudaFuncAttributeMaxDynamicSharedMemorySize, smem_bytes);
        rnn_steps<<<NCTA, BLK2, smem_bytes>>>(h0, Wh_w, Wh_b, out);
    }

    // Phase 3: reset barrier counters for the next graph replay
    reset_cnt<<<(L_ + 255) / 256, 256>>>();
}

// round 5
// speedup vs baseline: 2.6608x; 1.1912x over previous
#include <cuda_runtime.h>
#include <cuda_bf16.h>
#include <math.h>

// ============================================================================
// RNN: h_t = tanh(x_t @ Wi^T + bi + h_{t-1} @ Wh^T + bh)
// Phase 1: bf16 hi/lo split tensor-core GEMM (mma.sync.m16n8k16, fp32 accum,
//          3 passes: hi*hi + hi*lo + lo*hi). Split is done in-kernel while
//          staging tiles to SMEM -> no global scratch, fp32-level accuracy.
// Phase 2: persistent SIMT kernel (unchanged from R4): 128 CTAs x 512 thr,
//          k-lane layout, packed fma.rn.f32x2, butterfly reduction, global
//          barrier per step.
// Shapes hardcoded: L=512, B=128, D=H=1024 (fp32).
// ============================================================================

#define L_    512
#define B_    128
#define H_    1024
#define NCTA  128
#define BLK2  512
#define COLS  8
#define KT    128
#define NCH   (H_ / KT)
#define HBUF  (B_ * KT)

typedef unsigned long long ull;
typedef unsigned int u32;

__device__ unsigned g_cnt[L_];

// ---------------- f32x2 helpers ----------------
__device__ __forceinline__ ull pack2(float lo, float hi) {
    ull d;
    asm("mov.b64 %0, {%1, %2};" : "=l"(d) : "r"(__float_as_uint(lo)), "r"(__float_as_uint(hi)));
    return d;
}
__device__ __forceinline__ void unpack2(float& lo, float& hi, ull v) {
    unsigned a, b;
    asm("mov.b64 {%0, %1}, %2;" : "=r"(a), "=r"(b) : "l"(v));
    lo = __uint_as_float(a); hi = __uint_as_float(b);
}
__device__ __forceinline__ void fma2(ull& d, ull a, ull b) {
    asm("fma.rn.f32x2 %0, %1, %2, %0;" : "+l"(d) : "l"(a), "l"(b));
}
__device__ __forceinline__ ull add2(ull a, ull b) {
    ull d;
    asm("add.rn.f32x2 %0, %1, %2;" : "=l"(d) : "l"(a), "l"(b));
    return d;
}

// ---------------- cp.async helpers ----------------
__device__ __forceinline__ void cp_async16(float* smem_dst, const float* gsrc) {
    unsigned s = (unsigned)__cvta_generic_to_shared(smem_dst);
    asm volatile("cp.async.cg.shared.global [%0], [%1], 16;\n" :: "r"(s), "l"(gsrc));
}
__device__ __forceinline__ void cp_commit() { asm volatile("cp.async.commit_group;\n"); }
template <int N>
__device__ __forceinline__ void cp_wait() { asm volatile("cp.async.wait_group %0;\n" :: "n"(N)); }

// ============================================================================
// Phase 1: bf16-split tensor-core GEMM
// C[m,n] = sum_k A[m,k]*B[n,k] + bias[n];  M=65536, N=1024, K=1024
// Tile 128x128x32, 256 threads, 8 warps (4m x 2n), warp tile 32x64.
// ============================================================================
#define P1_BM 128
#define P1_BN 128
#define P1_BK 32
#define LDS_  40          // bf16 elements per smem row (32 + 8 pad) -> 80B stride

__device__ __forceinline__ void ldsm_x4(u32& r0, u32& r1, u32& r2, u32& r3, u32 addr) {
    asm volatile("ldmatrix.sync.aligned.m8n8.x4.shared.b16 {%0,%1,%2,%3}, [%4];"
                 : "=r"(r0), "=r"(r1), "=r"(r2), "=r"(r3) : "r"(addr));
}
__device__ __forceinline__ void mma_bf16(float* c, u32 a0, u32 a1, u32 a2, u32 a3,
                                         u32 b0, u32 b1) {
    asm volatile("mma.sync.aligned.m16n8k16.row.col.f32.bf16.bf16.f32 "
                 "{%0,%1,%2,%3}, {%4,%5,%6,%7}, {%8,%9}, {%0,%1,%2,%3};"
                 : "+f"(c[0]), "+f"(c[1]), "+f"(c[2]), "+f"(c[3])
                 : "r"(a0), "r"(a1), "r"(a2), "r"(a3), "r"(b0), "r"(b1));
}
// split one float into (hi, lo) bf16
__device__ __forceinline__ void split_bf16(float v, __nv_bfloat16& h, __nv_bfloat16& l) {
    h = __float2bfloat16(v);
    l = __float2bfloat16(v - __bfloat162float(h));
}
// convert float4 -> two packed uint2 (4 hi bf16, 4 lo bf16)
__device__ __forceinline__ void split4(float4 v, uint2& hi, uint2& lo) {
    __nv_bfloat16 h0,h1,h2,h3,l0,l1,l2,l3;
    split_bf16(v.x,h0,l0); split_bf16(v.y,h1,l1);
    split_bf16(v.z,h2,l2); split_bf16(v.w,h3,l3);
    __nv_bfloat162 ph0 = {h0,h1}, ph1 = {h2,h3}, pl0 = {l0,l1}, pl1 = {l2,l3};
    hi.x = *reinterpret_cast<u32*>(&ph0); hi.y = *reinterpret_cast<u32*>(&ph1);
    lo.x = *reinterpret_cast<u32*>(&pl0); lo.y = *reinterpret_cast<u32*>(&pl1);
}

__global__ void __launch_bounds__(256)
gemm_bf16split(const float* __restrict__ A, const float* __restrict__ B,
               const float* __restrict__ bias, float* __restrict__ C,
               int M, int N, int K)
{
    __shared__ __align__(16) __nv_bfloat16 sAh[P1_BM * LDS_];
    __shared__ __align__(16) __nv_bfloat16 sAl[P1_BM * LDS_];
    __shared__ __align__(16) __nv_bfloat16 sBh[P1_BN * LDS_];
    __shared__ __align__(16) __nv_bfloat16 sBl[P1_BN * LDS_];

    const int tid  = threadIdx.x;
    const int warp = tid >> 5;
    const int lane = tid & 31;
    const int wm   = warp & 3;          // warp row   (32 rows)
    const int wn   = warp >> 2;         // warp col   (64 cols)
    const int bm   = blockIdx.y * P1_BM;
    const int bn   = blockIdx.x * P1_BN;

    // per-thread load slots: 4 float4 each for A and B
    // f = tid + i*256 over 1024 slots: row = f>>3, c4 = f&7
    const float* agp[4];
    const float* bgp[4];
    int arow[4], ac4[4];
#pragma unroll
    for (int i = 0; i < 4; ++i) {
        int f = tid + i * 256;
        arow[i] = f >> 3; ac4[i] = f & 7;
        agp[i] = A + (size_t)(bm + arow[i]) * K + ac4[i] * 4;
        bgp[i] = B + (size_t)(bn + arow[i]) * K + ac4[i] * 4;
    }

    // ldmatrix base offsets (bytes within a plane)
    const u32 lrow = lane & 15;
    const u32 lkof = (lane >> 4) * 16;
    const u32 aoff0 = (wm * 32 + lrow) * (LDS_ * 2) + lkof;       // + mt*16*stride + ks*32
    const u32 boff0 = (wn * 64 + lrow) * (LDS_ * 2) + lkof;       // + np*16*stride + ks*32
    const u32 sAh_b = (u32)__cvta_generic_to_shared(sAh);
    const u32 sAl_b = (u32)__cvta_generic_to_shared(sAl);
    const u32 sBh_b = (u32)__cvta_generic_to_shared(sBh);
    const u32 sBl_b = (u32)__cvta_generic_to_shared(sBl);

    float acc[2][8][4];
#pragma unroll
    for (int mt = 0; mt < 2; ++mt)
#pragma unroll
        for (int nt = 0; nt < 8; ++nt)
#pragma unroll
            for (int q = 0; q < 4; ++q) acc[mt][nt][q] = 0.f;

    // prefetch tile 0
    float4 pa[4], pb[4];
#pragma unroll
    for (int i = 0; i < 4; ++i) {
        pa[i] = *reinterpret_cast<const float4*>(agp[i]);
        pb[i] = *reinterpret_cast<const float4*>(bgp[i]);
    }

    const int NKT = K / P1_BK;          // 32
    for (int kt = 0; kt < NKT; ++kt) {
        // stage current tile to smem (split to hi/lo)
#pragma unroll
        for (int i = 0; i < 4; ++i) {
            uint2 hi, lo;
            int e = arow[i] * LDS_ + ac4[i] * 4;
            split4(pa[i], hi, lo);
            *reinterpret_cast<uint2*>(&sAh[e]) = hi;
            *reinterpret_cast<uint2*>(&sAl[e]) = lo;
            split4(pb[i], hi, lo);
            *reinterpret_cast<uint2*>(&sBh[e]) = hi;
            *reinterpret_cast<uint2*>(&sBl[e]) = lo;
        }
        __syncthreads();

        // prefetch next tile
        if (kt + 1 < NKT) {
#pragma unroll
            for (int i = 0; i < 4; ++i) {
                pa[i] = *reinterpret_cast<const float4*>(agp[i] + (kt + 1) * P1_BK);
                pb[i] = *reinterpret_cast<const float4*>(bgp[i] + (kt + 1) * P1_BK);
            }
        }

        // MMA over the 2 k16 steps of this tile
#pragma unroll
        for (int ks = 0; ks < 2; ++ks) {
            const u32 kb = ks * 32;
            u32 ah[2][4], al[2][4];
#pragma unroll
            for (int mt = 0; mt < 2; ++mt) {
                u32 off = aoff0 + mt * 16 * (LDS_ * 2) + kb;
                ldsm_x4(ah[mt][0], ah[mt][1], ah[mt][2], ah[mt][3], sAh_b + off);
                ldsm_x4(al[mt][0], al[mt][1], al[mt][2], al[mt][3], sAl_b + off);
            }
#pragma unroll
            for (int np = 0; np < 4; ++np) {
                u32 off = boff0 + np * 16 * (LDS_ * 2) + kb;
                u32 bh0, bh1, bh2, bh3, bl0, bl1, bl2, bl3;
                ldsm_x4(bh0, bh1, bh2, bh3, sBh_b + off);
                ldsm_x4(bl0, bl1, bl2, bl3, sBl_b + off);
#pragma unroll
                for (int mt = 0; mt < 2; ++mt) {
                    // n-tile 2*np   : b-frags (bh0,bh2) / (bl0,bl2)
                    mma_bf16(acc[mt][2*np],   ah[mt][0],ah[mt][1],ah[mt][2],ah[mt][3], bh0, bh2);
                    mma_bf16(acc[mt][2*np],   ah[mt][0],ah[mt][1],ah[mt][2],ah[mt][3], bl0, bl2);
                    mma_bf16(acc[mt][2*np],   al[mt][0],al[mt][1],al[mt][2],al[mt][3], bh0, bh2);
                    // n-tile 2*np+1 : b-frags (bh1,bh3) / (bl1,bl3)
                    mma_bf16(acc[mt][2*np+1], ah[mt][0],ah[mt][1],ah[mt][2],ah[mt][3], bh1, bh3);
                    mma_bf16(acc[mt][2*np+1], ah[mt][0],ah[mt][1],ah[mt][2],ah[mt][3], bl1, bl3);
                    mma_bf16(acc[mt][2*np+1], al[mt][0],al[mt][1],al[mt][2],al[mt][3], bh1, bh3);
                }
            }
        }
        __syncthreads();
    }

    // epilogue: bias + store (float2 per half-tile-row)
    const int qrow = lane >> 2;        // 0..7
    const int qcol = (lane & 3) * 2;
#pragma unroll
    for (int mt = 0; mt < 2; ++mt) {
        const int r0 = bm + wm * 32 + mt * 16 + qrow;
#pragma unroll
        for (int nt = 0; nt < 8; ++nt) {
            const int c = bn + wn * 64 + nt * 8 + qcol;
            float2 bs = *reinterpret_cast<const float2*>(bias + c);
            float2 v0; v0.x = acc[mt][nt][0] + bs.x; v0.y = acc[mt][nt][1] + bs.y;
            float2 v1; v1.x = acc[mt][nt][2] + bs.x; v1.y = acc[mt][nt][3] + bs.y;
            *reinterpret_cast<float2*>(C + (size_t)r0 * N + c)       = v0;
            *reinterpret_cast<float2*>(C + (size_t)(r0 + 8) * N + c) = v1;
        }
    }
}

// ============================================================================
// Phase 2: persistent recurrence (unchanged from R4)
// ============================================================================
__device__ __forceinline__ void issue_chunk(const float* __restrict__ hp, int ch,
                                            float* __restrict__ dst, int tid) {
#pragma unroll
    for (int f = tid; f < B_ * KT / 4; f += BLK2) {
        int b  = f >> 5;
        int kv = f & 31;
        cp_async16(dst + b * KT + kv * 4, hp + (size_t)b * H_ + ch * KT + kv * 4);
    }
}

__global__ void __launch_bounds__(BLK2, 1)
rnn_steps(const float* __restrict__ h0, const float* __restrict__ Wh,
          const float* __restrict__ bh, float* __restrict__ out)
{
    extern __shared__ float smem[];
    float* wsm  = smem;                  // [COLS][H_]
    float* hbuf = smem + COLS * H_;      // 2 x [B_][KT]

    const int tid  = threadIdx.x;
    const int warp = tid >> 5;
    const int lane = tid & 31;
    const int n0   = blockIdx.x * COLS;
    const int r0   = warp * 8;

    for (int idx = tid; idx < COLS * (H_ / 4); idx += BLK2) {
        int c  = idx >> 8;
        int kv = idx & 255;
        float4 v = *reinterpret_cast<const float4*>(Wh + (size_t)(n0 + c) * H_ + kv * 4);
        *reinterpret_cast<float4*>(wsm + c * H_ + kv * 4) = v;
    }

    const int j  = (int)(__brev((unsigned)lane) >> 27);
    const int pj = j >> 3;
    const int cj = j & 7;
    const int row0 = r0 + 2 * pj;
    const int col  = n0 + cj;
    const float wb = bh[col];
    const size_t o_off0 = (size_t)row0 * H_ + col;
    __syncthreads();

    for (int t = 0; t < L_; ++t) {
        const float* hp = (t == 0) ? h0 : (out + (size_t)(t - 1) * B_ * H_);

        issue_chunk(hp, 0, hbuf, tid);        cp_commit();
        issue_chunk(hp, 1, hbuf + HBUF, tid); cp_commit();

        ull acc2[32];
#pragma unroll
        for (int i = 0; i < 32; ++i) acc2[i] = 0ull;

#pragma unroll 1
        for (int ch = 0; ch < NCH; ++ch) {
            if (ch < NCH - 1) cp_wait<1>(); else cp_wait<0>();
            __syncthreads();
            const float* hb = hbuf + (ch & 1) * HBUF;
#pragma unroll
            for (int kq = 0; kq < KT / 32; ++kq) {
                const int kl = kq * 32 + lane;
                const float* hpr = hb + (size_t)r0 * KT + kl;
                const float* wpr = wsm + ch * KT + kl;
                float h[8], w[8];
#pragma unroll
                for (int ri = 0; ri < 8; ++ri) h[ri] = hpr[ri * KT];
#pragma unroll
                for (int c = 0; c < 8; ++c)    w[c]  = wpr[c * H_];
                ull hp2[4], wd[8];
#pragma unroll
                for (int p = 0; p < 4; ++p) hp2[p] = pack2(h[2 * p], h[2 * p + 1]);
#pragma unroll
                for (int c = 0; c < 8; ++c) wd[c] = pack2(w[c], w[c]);
#pragma unroll
                for (int p = 0; p < 4; ++p)
#pragma unroll
                    for (int c = 0; c < 8; ++c)
                        fma2(acc2[p * 8 + c], hp2[p], wd[c]);
            }
            __syncthreads();
            if (ch + 2 < NCH) {
                issue_chunk(hp, ch + 2, hbuf + (ch & 1) * HBUF, tid);
                cp_commit();
            }
        }

        int half = 16;
#pragma unroll
        for (int d = 1; d < 32; d <<= 1) {
            const bool up = (lane & d) != 0;
#pragma unroll
            for (int i = 0; i < 16; ++i) {
                if (i < half) {
                    ull send = up ? acc2[i] : acc2[i + half];
                    ull keep = up ? acc2[i + half] : acc2[i];
                    ull recv = __shfl_xor_sync(0xffffffffu, send, d);
                    acc2[i] = add2(keep, recv);
                }
            }
            half >>= 1;
        }

        float a0, a1;
        unpack2(a0, a1, acc2[0]);
        float* ot = out + (size_t)t * B_ * H_;
        float v0 = tanhf(a0 + wb + ot[o_off0]);
        float v1 = tanhf(a1 + wb + ot[o_off0 + H_]);
        ot[o_off0]      = v0;
        ot[o_off0 + H_] = v1;

        if (t < L_ - 1) {
            __threadfence();
            __syncthreads();
            if (tid == 0) {
                atomicAdd(&g_cnt[t], 1u);
                while (((volatile unsigned*)g_cnt)[t] < NCTA) { __nanosleep(64); }
                __threadfence();
            }
            __syncthreads();
        }
    }
}

__global__ void reset_cnt() {
    int i = blockIdx.x * blockDim.x + threadIdx.x;
    if (i < L_) g_cnt[i] = 0;
}

// ---------------- launcher ----------------
extern "C" void kernel_launch(void* const* d_in, const int* in_sizes, int n_in,
                              void* d_out, int out_size)
{
    const float* x    = (const float*)d_in[0];  // [L,B,D]
    const float* h0   = (const float*)d_in[1];  // [B,H]
    const float* Wi_w = (const float*)d_in[2];  // [H,D]
    const float* Wi_b = (const float*)d_in[3];  // [H]
    const float* Wh_w = (const float*)d_in[4];  // [H,H]
    const float* Wh_b = (const float*)d_in[5];  // [H]
    float* out = (float*)d_out;                 // [L,B,H]

    // Phase 1: out = x @ Wi^T + bi  (tensor cores, bf16 split)
    {
        const int M1 = L_ * B_;
        dim3 grid(H_ / P1_BN, M1 / P1_BM);
        gemm_bf16split<<<grid, 256>>>(x, Wi_w, Wi_b, out, M1, H_, H_);
    }

    // Phase 2: persistent recurrence
    {
        const int smem_bytes = (COLS * H_ + 2 * HBUF) * (int)sizeof(float);
        cudaFuncSetAttribute(rnn_steps, cudaFuncAttributeMaxDynamicSharedMemorySize, smem_bytes);
        rnn_steps<<<NCTA, BLK2, smem_bytes>>>(h0, Wh_w, Wh_b, out);
    }

    // Phase 3: reset barrier counters for the next graph replay
    reset_cnt<<<(L_ + 255) / 256, 256>>>();
}

// round 6
// speedup vs baseline: 2.9962x; 1.1260x over previous
#include <cuda_runtime.h>
#include <cuda_bf16.h>
#include <math.h>

// ============================================================================
// RNN: h_t = tanh(x_t @ Wi^T + bi + h_{t-1} @ Wh^T + bh)
// Phase 1: bf16 hi/lo split tensor-core GEMM (unchanged from R5).
// Phase 2: persistent SIMT kernel, 128 CTAs x 512 thr, 2-D output split:
//          each CTA owns 32 batch-rows x 32 cols (4 batch-groups x 32
//          col-groups). Wh slice (32x1024 = 128KB) resident in SMEM; h
//          chunks (32x128 = 16KB) double-buffered via cp.async. k-lane
//          layout + packed fma.rn.f32x2 + butterfly reduction (as R4).
//          L2 h-traffic drops 4x vs the 1-D column split.
// Shapes hardcoded: L=512, B=128, D=H=1024 (fp32).
// ============================================================================

#define L_    512
#define B_    128
#define H_    1024
#define NCTA  128
#define BLK2  512
#define KT    128
#define NCH   (H_ / KT)
#define ROWS2 32                 // batch rows per CTA
#define COLS2 32                 // output cols per CTA
#define HBUF2 (ROWS2 * KT)       // floats per h stage (16KB)

typedef unsigned long long ull;
typedef unsigned int u32;

__device__ unsigned g_cnt[L_];

// ---------------- f32x2 helpers ----------------
__device__ __forceinline__ ull pack2(float lo, float hi) {
    ull d;
    asm("mov.b64 %0, {%1, %2};" : "=l"(d) : "r"(__float_as_uint(lo)), "r"(__float_as_uint(hi)));
    return d;
}
__device__ __forceinline__ void unpack2(float& lo, float& hi, ull v) {
    unsigned a, b;
    asm("mov.b64 {%0, %1}, %2;" : "=r"(a), "=r"(b) : "l"(v));
    lo = __uint_as_float(a); hi = __uint_as_float(b);
}
__device__ __forceinline__ void fma2(ull& d, ull a, ull b) {
    asm("fma.rn.f32x2 %0, %1, %2, %0;" : "+l"(d) : "l"(a), "l"(b));
}
__device__ __forceinline__ ull add2(ull a, ull b) {
    ull d;
    asm("add.rn.f32x2 %0, %1, %2;" : "=l"(d) : "l"(a), "l"(b));
    return d;
}

// ---------------- cp.async helpers ----------------
__device__ __forceinline__ void cp_async16(float* smem_dst, const float* gsrc) {
    unsigned s = (unsigned)__cvta_generic_to_shared(smem_dst);
    asm volatile("cp.async.cg.shared.global [%0], [%1], 16;\n" :: "r"(s), "l"(gsrc));
}
__device__ __forceinline__ void cp_commit() { asm volatile("cp.async.commit_group;\n"); }
template <int N>
__device__ __forceinline__ void cp_wait() { asm volatile("cp.async.wait_group %0;\n" :: "n"(N)); }

// ============================================================================
// Phase 1: bf16-split tensor-core GEMM (unchanged from R5)
// ============================================================================
#define P1_BM 128
#define P1_BN 128
#define P1_BK 32
#define LDS_  40

__device__ __forceinline__ void ldsm_x4(u32& r0, u32& r1, u32& r2, u32& r3, u32 addr) {
    asm volatile("ldmatrix.sync.aligned.m8n8.x4.shared.b16 {%0,%1,%2,%3}, [%4];"
                 : "=r"(r0), "=r"(r1), "=r"(r2), "=r"(r3) : "r"(addr));
}
__device__ __forceinline__ void mma_bf16(float* c, u32 a0, u32 a1, u32 a2, u32 a3,
                                         u32 b0, u32 b1) {
    asm volatile("mma.sync.aligned.m16n8k16.row.col.f32.bf16.bf16.f32 "
                 "{%0,%1,%2,%3}, {%4,%5,%6,%7}, {%8,%9}, {%0,%1,%2,%3};"
                 : "+f"(c[0]), "+f"(c[1]), "+f"(c[2]), "+f"(c[3])
                 : "r"(a0), "r"(a1), "r"(a2), "r"(a3), "r"(b0), "r"(b1));
}
__device__ __forceinline__ void split_bf16(float v, __nv_bfloat16& h, __nv_bfloat16& l) {
    h = __float2bfloat16(v);
    l = __float2bfloat16(v - __bfloat162float(h));
}
__device__ __forceinline__ void split4(float4 v, uint2& hi, uint2& lo) {
    __nv_bfloat16 h0,h1,h2,h3,l0,l1,l2,l3;
    split_bf16(v.x,h0,l0); split_bf16(v.y,h1,l1);
    split_bf16(v.z,h2,l2); split_bf16(v.w,h3,l3);
    __nv_bfloat162 ph0 = {h0,h1}, ph1 = {h2,h3}, pl0 = {l0,l1}, pl1 = {l2,l3};
    hi.x = *reinterpret_cast<u32*>(&ph0); hi.y = *reinterpret_cast<u32*>(&ph1);
    lo.x = *reinterpret_cast<u32*>(&pl0); lo.y = *reinterpret_cast<u32*>(&pl1);
}

__global__ void __launch_bounds__(256)
gemm_bf16split(const float* __restrict__ A, const float* __restrict__ B,
               const float* __restrict__ bias, float* __restrict__ C,
               int M, int N, int K)
{
    __shared__ __align__(16) __nv_bfloat16 sAh[P1_BM * LDS_];
    __shared__ __align__(16) __nv_bfloat16 sAl[P1_BM * LDS_];
    __shared__ __align__(16) __nv_bfloat16 sBh[P1_BN * LDS_];
    __shared__ __align__(16) __nv_bfloat16 sBl[P1_BN * LDS_];

    const int tid  = threadIdx.x;
    const int warp = tid >> 5;
    const int lane = tid & 31;
    const int wm   = warp & 3;
    const int wn   = warp >> 2;
    const int bm   = blockIdx.y * P1_BM;
    const int bn   = blockIdx.x * P1_BN;

    const float* agp[4];
    const float* bgp[4];
    int arow[4], ac4[4];
#pragma unroll
    for (int i = 0; i < 4; ++i) {
        int f = tid + i * 256;
        arow[i] = f >> 3; ac4[i] = f & 7;
        agp[i] = A + (size_t)(bm + arow[i]) * K + ac4[i] * 4;
        bgp[i] = B + (size_t)(bn + arow[i]) * K + ac4[i] * 4;
    }

    const u32 lrow = lane & 15;
    const u32 lkof = (lane >> 4) * 16;
    const u32 aoff0 = (wm * 32 + lrow) * (LDS_ * 2) + lkof;
    const u32 boff0 = (wn * 64 + lrow) * (LDS_ * 2) + lkof;
    const u32 sAh_b = (u32)__cvta_generic_to_shared(sAh);
    const u32 sAl_b = (u32)__cvta_generic_to_shared(sAl);
    const u32 sBh_b = (u32)__cvta_generic_to_shared(sBh);
    const u32 sBl_b = (u32)__cvta_generic_to_shared(sBl);

    float acc[2][8][4];
#pragma unroll
    for (int mt = 0; mt < 2; ++mt)
#pragma unroll
        for (int nt = 0; nt < 8; ++nt)
#pragma unroll
            for (int q = 0; q < 4; ++q) acc[mt][nt][q] = 0.f;

    float4 pa[4], pb[4];
#pragma unroll
    for (int i = 0; i < 4; ++i) {
        pa[i] = *reinterpret_cast<const float4*>(agp[i]);
        pb[i] = *reinterpret_cast<const float4*>(bgp[i]);
    }

    const int NKT = K / P1_BK;
    for (int kt = 0; kt < NKT; ++kt) {
#pragma unroll
        for (int i = 0; i < 4; ++i) {
            uint2 hi, lo;
            int e = arow[i] * LDS_ + ac4[i] * 4;
            split4(pa[i], hi, lo);
            *reinterpret_cast<uint2*>(&sAh[e]) = hi;
            *reinterpret_cast<uint2*>(&sAl[e]) = lo;
            split4(pb[i], hi, lo);
            *reinterpret_cast<uint2*>(&sBh[e]) = hi;
            *reinterpret_cast<uint2*>(&sBl[e]) = lo;
        }
        __syncthreads();

        if (kt + 1 < NKT) {
#pragma unroll
            for (int i = 0; i < 4; ++i) {
                pa[i] = *reinterpret_cast<const float4*>(agp[i] + (kt + 1) * P1_BK);
                pb[i] = *reinterpret_cast<const float4*>(bgp[i] + (kt + 1) * P1_BK);
            }
        }

#pragma unroll
        for (int ks = 0; ks < 2; ++ks) {
            const u32 kb = ks * 32;
            u32 ah[2][4], al[2][4];
#pragma unroll
            for (int mt = 0; mt < 2; ++mt) {
                u32 off = aoff0 + mt * 16 * (LDS_ * 2) + kb;
                ldsm_x4(ah[mt][0], ah[mt][1], ah[mt][2], ah[mt][3], sAh_b + off);
                ldsm_x4(al[mt][0], al[mt][1], al[mt][2], al[mt][3], sAl_b + off);
            }
#pragma unroll
            for (int np = 0; np < 4; ++np) {
                u32 off = boff0 + np * 16 * (LDS_ * 2) + kb;
                u32 bh0, bh1, bh2, bh3, bl0, bl1, bl2, bl3;
                ldsm_x4(bh0, bh1, bh2, bh3, sBh_b + off);
                ldsm_x4(bl0, bl1, bl2, bl3, sBl_b + off);
#pragma unroll
                for (int mt = 0; mt < 2; ++mt) {
                    mma_bf16(acc[mt][2*np],   ah[mt][0],ah[mt][1],ah[mt][2],ah[mt][3], bh0, bh2);
                    mma_bf16(acc[mt][2*np],   ah[mt][0],ah[mt][1],ah[mt][2],ah[mt][3], bl0, bl2);
                    mma_bf16(acc[mt][2*np],   al[mt][0],al[mt][1],al[mt][2],al[mt][3], bh0, bh2);
                    mma_bf16(acc[mt][2*np+1], ah[mt][0],ah[mt][1],ah[mt][2],ah[mt][3], bh1, bh3);
                    mma_bf16(acc[mt][2*np+1], ah[mt][0],ah[mt][1],ah[mt][2],ah[mt][3], bl1, bl3);
                    mma_bf16(acc[mt][2*np+1], al[mt][0],al[mt][1],al[mt][2],al[mt][3], bh1, bh3);
                }
            }
        }
        __syncthreads();
    }

    const int qrow = lane >> 2;
    const int qcol = (lane & 3) * 2;
#pragma unroll
    for (int mt = 0; mt < 2; ++mt) {
        const int r0 = bm + wm * 32 + mt * 16 + qrow;
#pragma unroll
        for (int nt = 0; nt < 8; ++nt) {
            const int c = bn + wn * 64 + nt * 8 + qcol;
            float2 bs = *reinterpret_cast<const float2*>(bias + c);
            float2 v0; v0.x = acc[mt][nt][0] + bs.x; v0.y = acc[mt][nt][1] + bs.y;
            float2 v1; v1.x = acc[mt][nt][2] + bs.x; v1.y = acc[mt][nt][3] + bs.y;
            *reinterpret_cast<float2*>(C + (size_t)r0 * N + c)       = v0;
            *reinterpret_cast<float2*>(C + (size_t)(r0 + 8) * N + c) = v1;
        }
    }
}

// ============================================================================
// Phase 2: persistent recurrence, 2-D output split (32 rows x 32 cols per CTA)
// ============================================================================
// Stream one 32(row) x 128(k) chunk of h_prev into dst (row-major, stride KT).
__device__ __forceinline__ void issue_chunk(const float* __restrict__ hp, int rb, int ch,
                                            float* __restrict__ dst, int tid) {
#pragma unroll
    for (int f = tid; f < ROWS2 * KT / 4; f += BLK2) {   // 1024 float4 slots, 2/thread
        int b  = f >> 5;                                  // local row 0..31
        int kv = f & 31;
        cp_async16(dst + b * KT + kv * 4, hp + (size_t)(rb + b) * H_ + ch * KT + kv * 4);
    }
}

__global__ void __launch_bounds__(BLK2, 1)
rnn_steps(const float* __restrict__ h0, const float* __restrict__ Wh,
          const float* __restrict__ bh, float* __restrict__ out)
{
    extern __shared__ float smem[];
    float* wsm  = smem;                    // [COLS2][H_] row-major (128KB)
    float* hbuf = smem + COLS2 * H_;       // 2 x [ROWS2][KT] (2 x 16KB)

    const int tid  = threadIdx.x;
    const int warp = tid >> 5;
    const int lane = tid & 31;
    const int cgrp = blockIdx.x & 31;      // col group 0..31
    const int bgrp = blockIdx.x >> 5;      // batch group 0..3
    const int n0   = cgrp * COLS2;
    const int rb   = bgrp * ROWS2;

    // warp sub-tile: 4 row-subs x 4 col-subs of 8x8
    const int wr = warp & 3;               // row sub-block
    const int wc = warp >> 2;              // col sub-block
    const int r0l = wr * 8;                // local row base in hbuf
    const int c0l = wc * 8;                // local col base in wsm

    // Load Wh slice once: wsm[c][k] = Wh[(n0+c)*H + k]
    for (int idx = tid; idx < COLS2 * (H_ / 4); idx += BLK2) {
        int c  = idx >> 8;                 // / (H_/4)
        int kv = idx & 255;
        float4 v = *reinterpret_cast<const float4*>(Wh + (size_t)(n0 + c) * H_ + kv * 4);
        *reinterpret_cast<float4*>(wsm + c * H_ + kv * 4) = v;
    }

    // Output mapping after butterfly: lane ends holding output rev5(lane)
    const int j  = (int)(__brev((unsigned)lane) >> 27);
    const int pj = j >> 3;                 // row-pair 0..3
    const int cj = j & 7;                  // col 0..7
    const int row0 = rb + r0l + 2 * pj;    // global batch row
    const int col  = n0 + c0l + cj;        // global output col
    const float wb = bh[col];
    const size_t o_off0 = (size_t)row0 * H_ + col;
    __syncthreads();

    for (int t = 0; t < L_; ++t) {
        const float* hp = (t == 0) ? h0 : (out + (size_t)(t - 1) * B_ * H_);

        issue_chunk(hp, rb, 0, hbuf, tid);         cp_commit();
        issue_chunk(hp, rb, 1, hbuf + HBUF2, tid); cp_commit();

        ull acc2[32];
#pragma unroll
        for (int i = 0; i < 32; ++i) acc2[i] = 0ull;

#pragma unroll 1
        for (int ch = 0; ch < NCH; ++ch) {
            if (ch < NCH - 1) cp_wait<1>(); else cp_wait<0>();
            __syncthreads();
            const float* hb = hbuf + (ch & 1) * HBUF2;
#pragma unroll
            for (int kq = 0; kq < KT / 32; ++kq) {
                const int kl = kq * 32 + lane;
                const float* hpr = hb + (size_t)r0l * KT + kl;
                const float* wpr = wsm + (size_t)c0l * H_ + ch * KT + kl;
                float h[8], w[8];
#pragma unroll
                for (int ri = 0; ri < 8; ++ri) h[ri] = hpr[ri * KT];
#pragma unroll
                for (int c = 0; c < 8; ++c)    w[c]  = wpr[c * H_];
                ull hp2[4], wd[8];
#pragma unroll
                for (int p = 0; p < 4; ++p) hp2[p] = pack2(h[2 * p], h[2 * p + 1]);
#pragma unroll
                for (int c = 0; c < 8; ++c) wd[c] = pack2(w[c], w[c]);
#pragma unroll
                for (int p = 0; p < 4; ++p)
#pragma unroll
                    for (int c = 0; c < 8; ++c)
                        fma2(acc2[p * 8 + c], hp2[p], wd[c]);
            }
            __syncthreads();
            if (ch + 2 < NCH) {
                issue_chunk(hp, rb, ch + 2, hbuf + (ch & 1) * HBUF2, tid);
                cp_commit();
            }
        }

        // Butterfly-split reduction over the 32 k-lanes
        int half = 16;
#pragma unroll
        for (int d = 1; d < 32; d <<= 1) {
            const bool up = (lane & d) != 0;
#pragma unroll
            for (int i = 0; i < 16; ++i) {
                if (i < half) {
                    ull send = up ? acc2[i] : acc2[i + half];
                    ull keep = up ? acc2[i + half] : acc2[i];
                    ull recv = __shfl_xor_sync(0xffffffffu, send, d);
                    acc2[i] = add2(keep, recv);
                }
            }
            half >>= 1;
        }

        float a0, a1;
        unpack2(a0, a1, acc2[0]);
        float* ot = out + (size_t)t * B_ * H_;
        float v0 = tanhf(a0 + wb + ot[o_off0]);
        float v1 = tanhf(a1 + wb + ot[o_off0 + H_]);
        ot[o_off0]      = v0;
        ot[o_off0 + H_] = v1;

        if (t < L_ - 1) {
            __threadfence();
            __syncthreads();
            if (tid == 0) {
                atomicAdd(&g_cnt[t], 1u);
                while (((volatile unsigned*)g_cnt)[t] < NCTA) { __nanosleep(64); }
                __threadfence();
            }
            __syncthreads();
        }
    }
}

__global__ void reset_cnt() {
    int i = blockIdx.x * blockDim.x + threadIdx.x;
    if (i < L_) g_cnt[i] = 0;
}

// ---------------- launcher ----------------
extern "C" void kernel_launch(void* const* d_in, const int* in_sizes, int n_in,
                              void* d_out, int out_size)
{
    const float* x    = (const float*)d_in[0];  // [L,B,D]
    const float* h0   = (const float*)d_in[1];  // [B,H]
    const float* Wi_w = (const float*)d_in[2];  // [H,D]
    const float* Wi_b = (const float*)d_in[3];  // [H]
    const float* Wh_w = (const float*)d_in[4];  // [H,H]
    const float* Wh_b = (const float*)d_in[5];  // [H]
    float* out = (float*)d_out;                 // [L,B,H]

    // Phase 1: out = x @ Wi^T + bi  (tensor cores, bf16 split)
    {
        const int M1 = L_ * B_;
        dim3 grid(H_ / P1_BN, M1 / P1_BM);
        gemm_bf16split<<<grid, 256>>>(x, Wi_w, Wi_b, out, M1, H_, H_);
    }

    // Phase 2: persistent recurrence (2-D split)
    {
        const int smem_bytes = (COLS2 * H_ + 2 * HBUF2) * (int)sizeof(float); // 163840
        cudaFuncSetAttribute(rnn_steps, cudaFuncAttributeMaxDynamicSharedMemorySize, smem_bytes);
        rnn_steps<<<NCTA, BLK2, smem_bytes>>>(h0, Wh_w, Wh_b, out);
    }

    // Phase 3: reset barrier counters for the next graph replay
    reset_cnt<<<(L_ + 255) / 256, 256>>>();
}

// round 7
// speedup vs baseline: 3.7322x; 1.2456x over previous
#include <cuda_runtime.h>
#include <cuda_bf16.h>
#include <math.h>

// ============================================================================
// RNN: h_t = tanh(x_t @ Wi^T + bi + h_{t-1} @ Wh^T + bh)
// Phase 1: bf16 hi/lo split tensor-core GEMM (unchanged from R5/R6).
// Phase 2: persistent TENSOR-CORE kernel. 128 CTAs x 512 thr, each CTA owns a
//          32(batch) x 32(col) output tile. Wh slice resident in SMEM as bf16
//          hi/lo. h carried step-to-step as bf16 hi/lo in __device__ ping-pong
//          scratch (converted once by the producer), streamed via a 4-slot
//          cp.async ring. 16 warps split K; mma.m16n8k16 x 3 passes
//          (hi*hi + hi*lo + lo*hi); cross-warp k-reduce in SMEM; fused
//          xi+tanh epilogue; global barrier per step.
// Shapes hardcoded: L=512, B=128, D=H=1024 (fp32).
// ============================================================================

#define L_    512
#define B_    128
#define H_    1024
#define NCTA  128
#define BLK2  512

typedef unsigned long long ull;
typedef unsigned int u32;

__device__ unsigned g_cnt[L_];                       // 0..510 step barriers, 511 pre-barrier
__device__ __nv_bfloat16 g_hh[2][B_ * H_];           // h hi, ping-pong
__device__ __nv_bfloat16 g_hl[2][B_ * H_];           // h lo, ping-pong

// ---------------- small helpers ----------------
__device__ __forceinline__ void unpack2(float& lo, float& hi, ull v) {
    unsigned a, b;
    asm("mov.b64 {%0, %1}, %2;" : "=r"(a), "=r"(b) : "l"(v));
    lo = __uint_as_float(a); hi = __uint_as_float(b);
}
__device__ __forceinline__ ull add2(ull a, ull b) {
    ull d;
    asm("add.rn.f32x2 %0, %1, %2;" : "=l"(d) : "l"(a), "l"(b));
    return d;
}
__device__ __forceinline__ void cp_async16g(char* smem_dst, const void* gsrc) {
    unsigned s = (unsigned)__cvta_generic_to_shared(smem_dst);
    asm volatile("cp.async.cg.shared.global [%0], [%1], 16;\n" :: "r"(s), "l"(gsrc));
}
__device__ __forceinline__ void cp_commit() { asm volatile("cp.async.commit_group;\n"); }
template <int N>
__device__ __forceinline__ void cp_wait() { asm volatile("cp.async.wait_group %0;\n" :: "n"(N)); }

__device__ __forceinline__ void ldsm_x4(u32& r0, u32& r1, u32& r2, u32& r3, u32 addr) {
    asm volatile("ldmatrix.sync.aligned.m8n8.x4.shared.b16 {%0,%1,%2,%3}, [%4];"
                 : "=r"(r0), "=r"(r1), "=r"(r2), "=r"(r3) : "r"(addr));
}
__device__ __forceinline__ void mma_bf16(float* c, u32 a0, u32 a1, u32 a2, u32 a3,
                                         u32 b0, u32 b1) {
    asm volatile("mma.sync.aligned.m16n8k16.row.col.f32.bf16.bf16.f32 "
                 "{%0,%1,%2,%3}, {%4,%5,%6,%7}, {%8,%9}, {%0,%1,%2,%3};"
                 : "+f"(c[0]), "+f"(c[1]), "+f"(c[2]), "+f"(c[3])
                 : "r"(a0), "r"(a1), "r"(a2), "r"(a3), "r"(b0), "r"(b1));
}
__device__ __forceinline__ void split_bf16(float v, __nv_bfloat16& h, __nv_bfloat16& l) {
    h = __float2bfloat16(v);
    l = __float2bfloat16(v - __bfloat162float(h));
}
__device__ __forceinline__ void split4(float4 v, uint2& hi, uint2& lo) {
    __nv_bfloat16 h0,h1,h2,h3,l0,l1,l2,l3;
    split_bf16(v.x,h0,l0); split_bf16(v.y,h1,l1);
    split_bf16(v.z,h2,l2); split_bf16(v.w,h3,l3);
    __nv_bfloat162 ph0 = {h0,h1}, ph1 = {h2,h3}, pl0 = {l0,l1}, pl1 = {l2,l3};
    hi.x = *reinterpret_cast<u32*>(&ph0); hi.y = *reinterpret_cast<u32*>(&ph1);
    lo.x = *reinterpret_cast<u32*>(&pl0); lo.y = *reinterpret_cast<u32*>(&pl1);
}

// ============================================================================
// Phase 1: bf16-split tensor-core GEMM (unchanged, proven)
// ============================================================================
#define P1_BM 128
#define P1_BN 128
#define P1_BK 32
#define LDS_  40

__global__ void __launch_bounds__(256)
gemm_bf16split(const float* __restrict__ A, const float* __restrict__ B,
               const float* __restrict__ bias, float* __restrict__ C,
               int M, int N, int K)
{
    __shared__ __align__(16) __nv_bfloat16 sAh[P1_BM * LDS_];
    __shared__ __align__(16) __nv_bfloat16 sAl[P1_BM * LDS_];
    __shared__ __align__(16) __nv_bfloat16 sBh[P1_BN * LDS_];
    __shared__ __align__(16) __nv_bfloat16 sBl[P1_BN * LDS_];

    const int tid  = threadIdx.x;
    const int warp = tid >> 5;
    const int lane = tid & 31;
    const int wm   = warp & 3;
    const int wn   = warp >> 2;
    const int bm   = blockIdx.y * P1_BM;
    const int bn   = blockIdx.x * P1_BN;

    const float* agp[4];
    const float* bgp[4];
    int arow[4], ac4[4];
#pragma unroll
    for (int i = 0; i < 4; ++i) {
        int f = tid + i * 256;
        arow[i] = f >> 3; ac4[i] = f & 7;
        agp[i] = A + (size_t)(bm + arow[i]) * K + ac4[i] * 4;
        bgp[i] = B + (size_t)(bn + arow[i]) * K + ac4[i] * 4;
    }

    const u32 lrow = lane & 15;
    const u32 lkof = (lane >> 4) * 16;
    const u32 aoff0 = (wm * 32 + lrow) * (LDS_ * 2) + lkof;
    const u32 boff0 = (wn * 64 + lrow) * (LDS_ * 2) + lkof;
    const u32 sAh_b = (u32)__cvta_generic_to_shared(sAh);
    const u32 sAl_b = (u32)__cvta_generic_to_shared(sAl);
    const u32 sBh_b = (u32)__cvta_generic_to_shared(sBh);
    const u32 sBl_b = (u32)__cvta_generic_to_shared(sBl);

    float acc[2][8][4];
#pragma unroll
    for (int mt = 0; mt < 2; ++mt)
#pragma unroll
        for (int nt = 0; nt < 8; ++nt)
#pragma unroll
            for (int q = 0; q < 4; ++q) acc[mt][nt][q] = 0.f;

    float4 pa[4], pb[4];
#pragma unroll
    for (int i = 0; i < 4; ++i) {
        pa[i] = *reinterpret_cast<const float4*>(agp[i]);
        pb[i] = *reinterpret_cast<const float4*>(bgp[i]);
    }

    const int NKT = K / P1_BK;
    for (int kt = 0; kt < NKT; ++kt) {
#pragma unroll
        for (int i = 0; i < 4; ++i) {
            uint2 hi, lo;
            int e = arow[i] * LDS_ + ac4[i] * 4;
            split4(pa[i], hi, lo);
            *reinterpret_cast<uint2*>(&sAh[e]) = hi;
            *reinterpret_cast<uint2*>(&sAl[e]) = lo;
            split4(pb[i], hi, lo);
            *reinterpret_cast<uint2*>(&sBh[e]) = hi;
            *reinterpret_cast<uint2*>(&sBl[e]) = lo;
        }
        __syncthreads();

        if (kt + 1 < NKT) {
#pragma unroll
            for (int i = 0; i < 4; ++i) {
                pa[i] = *reinterpret_cast<const float4*>(agp[i] + (kt + 1) * P1_BK);
                pb[i] = *reinterpret_cast<const float4*>(bgp[i] + (kt + 1) * P1_BK);
            }
        }

#pragma unroll
        for (int ks = 0; ks < 2; ++ks) {
            const u32 kb = ks * 32;
            u32 ah[2][4], al[2][4];
#pragma unroll
            for (int mt = 0; mt < 2; ++mt) {
                u32 off = aoff0 + mt * 16 * (LDS_ * 2) + kb;
                ldsm_x4(ah[mt][0], ah[mt][1], ah[mt][2], ah[mt][3], sAh_b + off);
                ldsm_x4(al[mt][0], al[mt][1], al[mt][2], al[mt][3], sAl_b + off);
            }
#pragma unroll
            for (int np = 0; np < 4; ++np) {
                u32 off = boff0 + np * 16 * (LDS_ * 2) + kb;
                u32 bh0, bh1, bh2, bh3, bl0, bl1, bl2, bl3;
                ldsm_x4(bh0, bh1, bh2, bh3, sBh_b + off);
                ldsm_x4(bl0, bl1, bl2, bl3, sBl_b + off);
#pragma unroll
                for (int mt = 0; mt < 2; ++mt) {
                    mma_bf16(acc[mt][2*np],   ah[mt][0],ah[mt][1],ah[mt][2],ah[mt][3], bh0, bh2);
                    mma_bf16(acc[mt][2*np],   ah[mt][0],ah[mt][1],ah[mt][2],ah[mt][3], bl0, bl2);
                    mma_bf16(acc[mt][2*np],   al[mt][0],al[mt][1],al[mt][2],al[mt][3], bh0, bh2);
                    mma_bf16(acc[mt][2*np+1], ah[mt][0],ah[mt][1],ah[mt][2],ah[mt][3], bh1, bh3);
                    mma_bf16(acc[mt][2*np+1], ah[mt][0],ah[mt][1],ah[mt][2],ah[mt][3], bl1, bl3);
                    mma_bf16(acc[mt][2*np+1], al[mt][0],al[mt][1],al[mt][2],al[mt][3], bh1, bh3);
                }
            }
        }
        __syncthreads();
    }

    const int qrow = lane >> 2;
    const int qcol = (lane & 3) * 2;
#pragma unroll
    for (int mt = 0; mt < 2; ++mt) {
        const int r0 = bm + wm * 32 + mt * 16 + qrow;
#pragma unroll
        for (int nt = 0; nt < 8; ++nt) {
            const int c = bn + wn * 64 + nt * 8 + qcol;
            float2 bs = *reinterpret_cast<const float2*>(bias + c);
            float2 v0; v0.x = acc[mt][nt][0] + bs.x; v0.y = acc[mt][nt][1] + bs.y;
            float2 v1; v1.x = acc[mt][nt][2] + bs.x; v1.y = acc[mt][nt][3] + bs.y;
            *reinterpret_cast<float2*>(C + (size_t)r0 * N + c)       = v0;
            *reinterpret_cast<float2*>(C + (size_t)(r0 + 8) * N + c) = v1;
        }
    }
}

// ============================================================================
// Phase 2: tensor-core persistent recurrence
// SMEM: WhHi[32][1032], WhLo[32][1032] (bf16, padded) = 129KB resident
//       ring: 4 slots x { hHi[32][136], hLo[32][136] } bf16 = 68KB (reused as
//             fp32 partial buffer [16][1024] during reduction)
// ============================================================================
#define WH_STRIDE   1032                       // bf16 elems per Wh row (pad 8)
#define WH_PLANE    (32 * WH_STRIDE * 2)       // bytes per Wh plane (66048)
#define CH_STRIDE   136                        // bf16 elems per h-chunk row
#define CH_PLANE    (32 * CH_STRIDE * 2)       // bytes per h-chunk plane (8704)
#define SLOT_BYTES  (2 * CH_PLANE)             // hi+lo (17408)
#define RING_OFF    (2 * WH_PLANE)             // 132096
#define SMEM2_BYTES (RING_OFF + 4 * SLOT_BYTES) // 201728

// stream one 32-row x 128-k bf16 chunk (hi+lo) of h into a ring slot
__device__ __forceinline__ void issue_hchunk(const __nv_bfloat16* __restrict__ srcH,
                                             const __nv_bfloat16* __restrict__ srcL,
                                             int rb, int ch, char* slot, int tid) {
#pragma unroll
    for (int s = 0; s < 2; ++s) {
        int f     = tid + s * BLK2;            // 0..1023
        int plane = f >> 9;                    // 0 = hi, 1 = lo
        int idx   = f & 511;
        int row   = idx >> 4;                  // 0..31
        int seg   = idx & 15;                  // 16B (=8 bf16) segment
        const __nv_bfloat16* src = (plane ? srcL : srcH)
                                   + (size_t)(rb + row) * H_ + ch * 128 + seg * 8;
        cp_async16g(slot + plane * CH_PLANE + row * (CH_STRIDE * 2) + seg * 16, src);
    }
}

__global__ void __launch_bounds__(BLK2, 1)
rnn_steps_tc(const float* __restrict__ h0, const float* __restrict__ Wh,
             const float* __restrict__ bh, float* __restrict__ out)
{
    extern __shared__ __align__(16) char smem2[];
    __nv_bfloat16* whh = reinterpret_cast<__nv_bfloat16*>(smem2);
    __nv_bfloat16* whl = whh + 32 * WH_STRIDE;
    char* ring = smem2 + RING_OFF;

    const int tid  = threadIdx.x;
    const int warp = tid >> 5;
    const int lane = tid & 31;
    const int cgrp = blockIdx.x & 31;
    const int bgrp = blockIdx.x >> 5;
    const int n0   = cgrp * 32;
    const int rb   = bgrp * 32;

    // ---- convert this CTA's Wh slice to bf16 hi/lo in SMEM ----
    for (int idx = tid; idx < 32 * 256; idx += BLK2) {
        int c  = idx >> 8;
        int kv = idx & 255;
        float4 v = *reinterpret_cast<const float4*>(Wh + (size_t)(n0 + c) * H_ + kv * 4);
        uint2 hi, lo;
        split4(v, hi, lo);
        *reinterpret_cast<uint2*>(whh + c * WH_STRIDE + kv * 4) = hi;
        *reinterpret_cast<uint2*>(whl + c * WH_STRIDE + kv * 4) = lo;
    }

    // ---- convert h0 -> g_hh[0]/g_hl[0] (each CTA a disjoint 1024-elem piece) ----
    {
        int base = blockIdx.x * 1024 + tid * 2;
        float2 v = *reinterpret_cast<const float2*>(h0 + base);
        __nv_bfloat16 ha, la, hb, lb;
        split_bf16(v.x, ha, la);
        split_bf16(v.y, hb, lb);
        __nv_bfloat162 ph = {ha, hb}, pl = {la, lb};
        reinterpret_cast<u32*>(g_hh[0])[base >> 1] = *reinterpret_cast<u32*>(&ph);
        reinterpret_cast<u32*>(g_hl[0])[base >> 1] = *reinterpret_cast<u32*>(&pl);
    }
    __threadfence();
    __syncthreads();
    if (tid == 0) {
        atomicAdd(&g_cnt[511], 1u);
        while (((volatile unsigned*)g_cnt)[511] < NCTA) { __nanosleep(64); }
        __threadfence();
    }
    __syncthreads();

    // ---- per-thread constants ----
    const u32 lrow  = lane & 15;
    const u32 lkof  = (lane >> 4) * 16;
    const int myk16 = warp & 7;                 // k16 index within a chunk
    const int chpar = warp >> 3;                // chunk parity handled by this warp
    const u32 whh_b = (u32)__cvta_generic_to_shared(whh);
    const u32 whl_b = (u32)__cvta_generic_to_shared(whl);

    // reduction / epilogue mapping: thread e owns local elems (2e, 2e+1)
    const int e     = tid;
    const int lrow2 = e >> 4;                   // local row 0..31
    const int lcol2 = (e & 15) * 2;             // local col (even)
    const int grow  = rb + lrow2;
    const int gcol  = n0 + lcol2;
    const float2 wb = *reinterpret_cast<const float2*>(bh + gcol);
    const size_t o_off = (size_t)grow * H_ + gcol;

    float* pbuf = reinterpret_cast<float*>(ring);
    const int prow  = lane >> 2;
    const int pcol2 = (lane & 3) * 2;

    for (int t = 0; t < L_; ++t) {
        const __nv_bfloat16* srcH = g_hh[t & 1];
        const __nv_bfloat16* srcL = g_hl[t & 1];

        // issue chunks 0..3
#pragma unroll
        for (int ch = 0; ch < 4; ++ch) {
            issue_hchunk(srcH, srcL, rb, ch, ring + (ch & 3) * SLOT_BYTES, tid);
            cp_commit();
        }

        float acc[2][4][4];
#pragma unroll
        for (int mt = 0; mt < 2; ++mt)
#pragma unroll
            for (int nt = 0; nt < 4; ++nt)
#pragma unroll
                for (int q = 0; q < 4; ++q) acc[mt][nt][q] = 0.f;

#pragma unroll
        for (int r = 0; r < 4; ++r) {
            if (r < 3) cp_wait<2>(); else cp_wait<0>();
            __syncthreads();

            const int ch = 2 * r + chpar;
            const u32 slot_hi = (u32)__cvta_generic_to_shared(ring + (ch & 3) * SLOT_BYTES);
            const u32 slot_lo = slot_hi + CH_PLANE;
            const int kglob   = ch * 128 + myk16 * 16;

            u32 ah[2][4], al[2][4];
#pragma unroll
            for (int mt = 0; mt < 2; ++mt) {
                u32 off = (mt * 16 + lrow) * (CH_STRIDE * 2) + myk16 * 32 + lkof;
                ldsm_x4(ah[mt][0], ah[mt][1], ah[mt][2], ah[mt][3], slot_hi + off);
                ldsm_x4(al[mt][0], al[mt][1], al[mt][2], al[mt][3], slot_lo + off);
            }
#pragma unroll
            for (int np = 0; np < 2; ++np) {
                u32 boff = (np * 16 + lrow) * (WH_STRIDE * 2) + kglob * 2 + lkof;
                u32 bh0, bh1, bh2, bh3, bl0, bl1, bl2, bl3;
                ldsm_x4(bh0, bh1, bh2, bh3, whh_b + boff);
                ldsm_x4(bl0, bl1, bl2, bl3, whl_b + boff);
#pragma unroll
                for (int mt = 0; mt < 2; ++mt) {
                    mma_bf16(acc[mt][2*np],   ah[mt][0],ah[mt][1],ah[mt][2],ah[mt][3], bh0, bh2);
                    mma_bf16(acc[mt][2*np],   ah[mt][0],ah[mt][1],ah[mt][2],ah[mt][3], bl0, bl2);
                    mma_bf16(acc[mt][2*np],   al[mt][0],al[mt][1],al[mt][2],al[mt][3], bh0, bh2);
                    mma_bf16(acc[mt][2*np+1], ah[mt][0],ah[mt][1],ah[mt][2],ah[mt][3], bh1, bh3);
                    mma_bf16(acc[mt][2*np+1], ah[mt][0],ah[mt][1],ah[mt][2],ah[mt][3], bl1, bl3);
                    mma_bf16(acc[mt][2*np+1], al[mt][0],al[mt][1],al[mt][2],al[mt][3], bh1, bh3);
                }
            }
            __syncthreads();
            if (r < 2) {
                issue_hchunk(srcH, srcL, rb, 2*r + 4, ring + ((2*r)     & 3) * SLOT_BYTES, tid);
                cp_commit();
                issue_hchunk(srcH, srcL, rb, 2*r + 5, ring + ((2*r + 1) & 3) * SLOT_BYTES, tid);
                cp_commit();
            }
        }

        // ---- store partials (ring smem reused as [16][1024] fp32) ----
#pragma unroll
        for (int mt = 0; mt < 2; ++mt)
#pragma unroll
            for (int nt = 0; nt < 4; ++nt) {
                int b = warp * 1024 + (mt * 16 + prow) * 32 + nt * 8 + pcol2;
                float2 v0 = {acc[mt][nt][0], acc[mt][nt][1]};
                float2 v1 = {acc[mt][nt][2], acc[mt][nt][3]};
                *reinterpret_cast<float2*>(&pbuf[b])          = v0;
                *reinterpret_cast<float2*>(&pbuf[b + 8 * 32]) = v1;
            }
        __syncthreads();

        // ---- 16-way k-reduction + fused epilogue ----
        ull s2 = *reinterpret_cast<const ull*>(&pbuf[2 * e]);
#pragma unroll
        for (int w = 1; w < 16; ++w)
            s2 = add2(s2, *reinterpret_cast<const ull*>(&pbuf[w * 1024 + 2 * e]));
        float s0, s1;
        unpack2(s0, s1, s2);

        float* ot = out + (size_t)t * B_ * H_;
        float2 xi = *reinterpret_cast<const float2*>(ot + o_off);
        float v0 = tanhf(s0 + wb.x + xi.x);
        float v1 = tanhf(s1 + wb.y + xi.y);
        float2 vv = {v0, v1};
        *reinterpret_cast<float2*>(ot + o_off) = vv;

        __nv_bfloat16 ha, la, hb2, lb2;
        split_bf16(v0, ha, la);
        split_bf16(v1, hb2, lb2);
        __nv_bfloat162 ph = {ha, hb2}, pl = {la, lb2};
        const int nxt = (t + 1) & 1;
        reinterpret_cast<u32*>(g_hh[nxt])[o_off >> 1] = *reinterpret_cast<u32*>(&ph);
        reinterpret_cast<u32*>(g_hl[nxt])[o_off >> 1] = *reinterpret_cast<u32*>(&pl);

        if (t < L_ - 1) {
            __threadfence();
            __syncthreads();
            if (tid == 0) {
                atomicAdd(&g_cnt[t], 1u);
                while (((volatile unsigned*)g_cnt)[t] < NCTA) { __nanosleep(64); }
                __threadfence();
            }
            __syncthreads();
        }
    }
}

__global__ void reset_cnt() {
    int i = blockIdx.x * blockDim.x + threadIdx.x;
    if (i < L_) g_cnt[i] = 0;
}

// ---------------- launcher ----------------
extern "C" void kernel_launch(void* const* d_in, const int* in_sizes, int n_in,
                              void* d_out, int out_size)
{
    const float* x    = (const float*)d_in[0];  // [L,B,D]
    const float* h0   = (const float*)d_in[1];  // [B,H]
    const float* Wi_w = (const float*)d_in[2];  // [H,D]
    const float* Wi_b = (const float*)d_in[3];  // [H]
    const float* Wh_w = (const float*)d_in[4];  // [H,H]
    const float* Wh_b = (const float*)d_in[5];  // [H]
    float* out = (float*)d_out;                 // [L,B,H]

    // Phase 1: out = x @ Wi^T + bi  (tensor cores, bf16 split)
    {
        const int M1 = L_ * B_;
        dim3 grid(H_ / P1_BN, M1 / P1_BM);
        gemm_bf16split<<<grid, 256>>>(x, Wi_w, Wi_b, out, M1, H_, H_);
    }

    // Phase 2: persistent tensor-core recurrence
    {
        cudaFuncSetAttribute(rnn_steps_tc, cudaFuncAttributeMaxDynamicSharedMemorySize,
                             SMEM2_BYTES);
        rnn_steps_tc<<<NCTA, BLK2, SMEM2_BYTES>>>(h0, Wh_w, Wh_b, out);
    }

    // Phase 3: reset barrier counters for the next graph replay
    reset_cnt<<<(L_ + 255) / 256, 256>>>();
}